// round 4
// baseline (speedup 1.0000x reference)
#include <cstdint>
#include <cuda_runtime.h>
#include <cuda_bf16.h>
#include <mma.h>

using namespace nvcuda;

#define BATCH 32
#define TLEN  512
#define DDIM  1024
#define K2    2048             // doubled K for hi/lo interleaved copy-gate GEMM
#define MROWS (BATCH * TLEN)   // 16384

#define BM 128
#define BN 128
#define BK 32

// ---------------- scratch (__device__ globals; no allocation allowed) ----------------
__device__ __nv_bfloat16 g_aq [(size_t)MROWS * DDIM];   // quantized activations (ints, exact in bf16)
__device__ float         g_inv_s[MROWS];                // per-row 1/s
__device__ __nv_bfloat16 g_xhl[(size_t)MROWS * K2];     // interleaved hi/lo split of raw x
__device__ __nv_bfloat16 g_wf [(size_t)DDIM * DDIM];    // sign(W_f)
__device__ __nv_bfloat16 g_wc [(size_t)DDIM * DDIM];    // sign(W_c)
__device__ __nv_bfloat16 g_wgs[(size_t)DDIM * DDIM];    // sign(W_g)
__device__ __nv_bfloat16 g_wg2[(size_t)DDIM * K2];      // W_g rows duplicated along K (for hi/lo)
__device__ float g_F [(size_t)MROWS * DDIM];            // raw accumulators (activation in scan)
__device__ float g_C [(size_t)MROWS * DDIM];
__device__ float g_G [(size_t)MROWS * DDIM];
__device__ float g_CG[(size_t)MROWS * DDIM];

__device__ __forceinline__ float sigmoidf_(float z) { return 1.0f / (1.0f + expf(-z)); }

__device__ __forceinline__ void cp_async16(void* smem, const void* gmem) {
    uint32_t s = (uint32_t)__cvta_generic_to_shared(smem);
    asm volatile("cp.async.cg.shared.global [%0], [%1], 16;\n" :: "r"(s), "l"(gmem));
}
__device__ __forceinline__ void cp_commit() { asm volatile("cp.async.commit_group;\n"); }
template <int N>
__device__ __forceinline__ void cp_wait() { asm volatile("cp.async.wait_group %0;\n" :: "n"(N)); }

// ---------------- weight conversion ----------------
__global__ void conv_w_kernel(const float* __restrict__ wf,
                              const float* __restrict__ wc,
                              const float* __restrict__ wg) {
    int i = blockIdx.x * 256 + threadIdx.x;
    if (i >= DDIM * DDIM) return;
    float a = wf[i], b = wc[i], c = wg[i];
    g_wf [i] = __float2bfloat16((a > 0.f) ? 1.f : ((a < 0.f) ? -1.f : 0.f));
    g_wc [i] = __float2bfloat16((b > 0.f) ? 1.f : ((b < 0.f) ? -1.f : 0.f));
    g_wgs[i] = __float2bfloat16((c > 0.f) ? 1.f : ((c < 0.f) ? -1.f : 0.f));
    __nv_bfloat16 cb = __float2bfloat16(c);   // ternary -> exact in bf16
    int n = i >> 10, j = i & 1023;
    size_t o2 = (size_t)n * K2 + 2 * j;
    g_wg2[o2] = cb; g_wg2[o2 + 1] = cb;
}

// ---------------- rmsnorm + act_quant + hi/lo split (one block per row) ----------------
__global__ __launch_bounds__(256) void prep_kernel(const float* __restrict__ x,
                                                   const float* __restrict__ scale) {
    __shared__ float red[256];
    int m = blockIdx.x;
    int t = threadIdx.x;
    const float4* xr = (const float4*)(x + (size_t)m * DDIM);
    float4 xv = xr[t];
    float4 sv = ((const float4*)scale)[t];

    float ss = xv.x * xv.x + xv.y * xv.y + xv.z * xv.z + xv.w * xv.w;
    red[t] = ss; __syncthreads();
    for (int s = 128; s > 0; s >>= 1) { if (t < s) red[t] += red[t + s]; __syncthreads(); }
    float rstd = rsqrtf(red[0] * (1.0f / DDIM) + 1e-5f);
    __syncthreads();

    float y0 = sv.x * xv.x * rstd, y1 = sv.y * xv.y * rstd;
    float y2 = sv.z * xv.z * rstd, y3 = sv.w * xv.w * rstd;
    float am = fmaxf(fmaxf(fabsf(y0), fabsf(y1)), fmaxf(fabsf(y2), fabsf(y3)));
    red[t] = am; __syncthreads();
    for (int s = 128; s > 0; s >>= 1) { if (t < s) red[t] = fmaxf(red[t], red[t + s]); __syncthreads(); }
    float amax = red[0];

    float s_q = fminf(fmaxf(127.0f / (amax + 1e-5f), 0.001f), 1000.0f);
    if (t == 0) g_inv_s[m] = 1.0f / s_q;

    float q0 = fminf(fmaxf(rintf(s_q * y0), -128.f), 127.f);
    float q1 = fminf(fmaxf(rintf(s_q * y1), -128.f), 127.f);
    float q2 = fminf(fmaxf(rintf(s_q * y2), -128.f), 127.f);
    float q3 = fminf(fmaxf(rintf(s_q * y3), -128.f), 127.f);

    union { __nv_bfloat16 h[4]; uint2 u; } pq;
    pq.h[0] = __float2bfloat16(q0); pq.h[1] = __float2bfloat16(q1);
    pq.h[2] = __float2bfloat16(q2); pq.h[3] = __float2bfloat16(q3);

    // interleaved hi/lo: [hi0, lo0, hi1, lo1, ...]
    union { __nv_bfloat16 h[8]; uint4 u; } phl;
    float xa[4] = {xv.x, xv.y, xv.z, xv.w};
#pragma unroll
    for (int i = 0; i < 4; i++) {
        __nv_bfloat16 hi = __float2bfloat16(xa[i]);
        phl.h[2 * i]     = hi;
        phl.h[2 * i + 1] = __float2bfloat16(xa[i] - __bfloat162float(hi));
    }
    *(uint2*)&g_aq [(size_t)m * DDIM + t * 4]  = pq.u;
    *(uint4*)&g_xhl[(size_t)m * K2   + t * 8]  = phl.u;
}

// ---------------- 3 quantized GEMMs, fused via blockIdx.z, 2-stage cp.async pipeline ----
// Raw accumulators stored to gmem; scale+bias+activation applied in the scan.
__global__ __launch_bounds__(256) void gemm_q3_kernel() {
    int mode = blockIdx.z;
    const __nv_bfloat16* __restrict__ W = (mode == 0) ? g_wf : (mode == 1) ? g_wc : g_wgs;
    float* __restrict__ out = (mode == 0) ? g_F : (mode == 1) ? g_C : g_G;

    __shared__ __nv_bfloat16 As[2][BM][BK + 8];   // row stride 80B (16B mult)
    __shared__ __nv_bfloat16 Bs[2][BK][BN + 8];   // row stride 272B (16B mult)

    int tid = threadIdx.x;
    int warpId = tid >> 5;
    int wm = warpId & 3, wn = warpId >> 2;        // 4x2 warps, warp tile 32x64
    int bm = blockIdx.x * BM, bn = blockIdx.y * BN;

    wmma::fragment<wmma::accumulator, 16, 16, 16, float> acc[2][4];
#pragma unroll
    for (int i = 0; i < 2; i++)
#pragma unroll
        for (int j = 0; j < 4; j++) wmma::fill_fragment(acc[i][j], 0.0f);

    auto issue = [&](int k0, int buf) {
#pragma unroll
        for (int i = 0; i < 2; i++) {
            int ci = tid + i * 256;
            int r  = ci >> 2,  c8  = (ci & 3)  * 8;
            cp_async16(&As[buf][r][c8], &g_aq[(size_t)(bm + r) * DDIM + k0 + c8]);
            int rb = ci >> 4,  cb8 = (ci & 15) * 8;
            cp_async16(&Bs[buf][rb][cb8], &W[(size_t)(k0 + rb) * DDIM + bn + cb8]);
        }
    };

    issue(0, 0); cp_commit();
    const int NK = DDIM / BK;  // 32
    for (int kt = 0; kt < NK; ++kt) {
        if (kt + 1 < NK) { issue((kt + 1) * BK, (kt + 1) & 1); cp_commit(); cp_wait<1>(); }
        else             { cp_wait<0>(); }
        __syncthreads();
        int buf = kt & 1;
#pragma unroll
        for (int ks = 0; ks < BK; ks += 16) {
            wmma::fragment<wmma::matrix_a, 16, 16, 16, __nv_bfloat16, wmma::row_major> af[2];
            wmma::fragment<wmma::matrix_b, 16, 16, 16, __nv_bfloat16, wmma::row_major> bfr[4];
#pragma unroll
            for (int i = 0; i < 2; i++)
                wmma::load_matrix_sync(af[i], &As[buf][wm * 32 + i * 16][ks], BK + 8);
#pragma unroll
            for (int j = 0; j < 4; j++)
                wmma::load_matrix_sync(bfr[j], &Bs[buf][ks][wn * 64 + j * 16], BN + 8);
#pragma unroll
            for (int i = 0; i < 2; i++)
#pragma unroll
                for (int j = 0; j < 4; j++)
                    wmma::mma_sync(acc[i][j], af[i], bfr[j], acc[i][j]);
        }
        __syncthreads();
    }

#pragma unroll
    for (int i = 0; i < 2; i++)
#pragma unroll
        for (int j = 0; j < 4; j++) {
            int gm = bm + wm * 32 + i * 16;
            int gn = bn + wn * 64 + j * 16;
            wmma::store_matrix_sync(&out[(size_t)gm * DDIM + gn], acc[i][j], DDIM,
                                    wmma::mem_row_major);
        }
}

// ---------------- copy-gate GEMM: CG_raw = x @ Wg^T via interleaved hi/lo (K=2048) ------
__global__ __launch_bounds__(256) void gemm_cg_kernel() {
    __shared__ __nv_bfloat16 As[2][BM][BK + 8];   // x hi/lo interleaved, row-major
    __shared__ __nv_bfloat16 Bs[2][BN][BK + 8];   // Wg2 rows (n), col-major matrix_b

    int tid = threadIdx.x;
    int warpId = tid >> 5;
    int wm = warpId & 3, wn = warpId >> 2;
    int bm = blockIdx.x * BM, bn = blockIdx.y * BN;

    wmma::fragment<wmma::accumulator, 16, 16, 16, float> acc[2][4];
#pragma unroll
    for (int i = 0; i < 2; i++)
#pragma unroll
        for (int j = 0; j < 4; j++) wmma::fill_fragment(acc[i][j], 0.0f);

    auto issue = [&](int k0, int buf) {
#pragma unroll
        for (int i = 0; i < 2; i++) {
            int ci = tid + i * 256;
            int r = ci >> 2, c8 = (ci & 3) * 8;
            cp_async16(&As[buf][r][c8], &g_xhl[(size_t)(bm + r) * K2 + k0 + c8]);
            cp_async16(&Bs[buf][r][c8], &g_wg2[(size_t)(bn + r) * K2 + k0 + c8]);
        }
    };

    issue(0, 0); cp_commit();
    const int NK = K2 / BK;  // 64
    for (int kt = 0; kt < NK; ++kt) {
        if (kt + 1 < NK) { issue((kt + 1) * BK, (kt + 1) & 1); cp_commit(); cp_wait<1>(); }
        else             { cp_wait<0>(); }
        __syncthreads();
        int buf = kt & 1;
#pragma unroll
        for (int ks = 0; ks < BK; ks += 16) {
            wmma::fragment<wmma::matrix_a, 16, 16, 16, __nv_bfloat16, wmma::row_major> af[2];
            wmma::fragment<wmma::matrix_b, 16, 16, 16, __nv_bfloat16, wmma::col_major> bfr[4];
#pragma unroll
            for (int i = 0; i < 2; i++)
                wmma::load_matrix_sync(af[i], &As[buf][wm * 32 + i * 16][ks], BK + 8);
#pragma unroll
            for (int j = 0; j < 4; j++)
                wmma::load_matrix_sync(bfr[j], &Bs[buf][wn * 64 + j * 16][ks], BK + 8);
#pragma unroll
            for (int i = 0; i < 2; i++)
#pragma unroll
                for (int j = 0; j < 4; j++)
                    wmma::mma_sync(acc[i][j], af[i], bfr[j], acc[i][j]);
        }
        __syncthreads();
    }

#pragma unroll
    for (int i = 0; i < 2; i++)
#pragma unroll
        for (int j = 0; j < 4; j++) {
            int gm = bm + wm * 32 + i * 16;
            int gn = bn + wn * 64 + j * 16;
            wmma::store_matrix_sync(&g_CG[(size_t)gm * DDIM + gn], acc[i][j], DDIM,
                                    wmma::mem_row_major);
        }
}

// ---------------- elementwise recurrence + fused activations ----------------
__global__ __launch_bounds__(128) void scan_kernel(const float* __restrict__ x,
                                                   const int* __restrict__ seqlen,
                                                   const float* __restrict__ bfv,
                                                   const float* __restrict__ bcv,
                                                   const float* __restrict__ bgv,
                                                   float* __restrict__ out) {
    int gid = blockIdx.x * blockDim.x + threadIdx.x;  // 0 .. 32767
    int b = gid >> 10;
    int d = gid & (DDIM - 1);
    int len = seqlen[b];
    float bf_ = bfv[d], bc_ = bcv[d], bg_ = bgv[d];
    const float* __restrict__ invp = g_inv_s + b * TLEN;
    size_t base = ((size_t)b * TLEN) * DDIM + d;
    float h = 0.0f;
#pragma unroll 8
    for (int t = 0; t < TLEN; t++) {
        size_t off = base + (size_t)t * DDIM;
        float inv = invp[t];
        float f  = sigmoidf_(g_F[off] * inv + bf_);
        float zc = g_C[off] * inv + bc_;
        float c  = zc * sigmoidf_(zc);
        float g  = sigmoidf_(g_G[off] * inv + bg_);
        float cg = sigmoidf_(g_CG[off]);
        float xv = x[off];
        float hn = f * h + (1.0f - f) * c;
        float o  = g * hn;
        h = cg * xv + (1.0f - cg) * hn;
        out[off] = (t < len) ? o : 0.0f;
    }
}

// ---------------- launcher ----------------
extern "C" void kernel_launch(void* const* d_in, const int* in_sizes, int n_in,
                              void* d_out, int out_size) {
    const float* x      = (const float*)d_in[0];
    const int*   seqlen = (const int*)  d_in[1];
    const float* scale  = (const float*)d_in[2];
    const float* Wf     = (const float*)d_in[3];
    const float* Wc     = (const float*)d_in[4];
    const float* Wg     = (const float*)d_in[5];
    const float* bf     = (const float*)d_in[6];
    const float* bc     = (const float*)d_in[7];
    const float* bg     = (const float*)d_in[8];
    float* out = (float*)d_out;

    conv_w_kernel<<<(DDIM * DDIM + 255) / 256, 256>>>(Wf, Wc, Wg);
    prep_kernel<<<MROWS, 256>>>(x, scale);

    dim3 gridq(MROWS / BM, DDIM / BN, 3);  // 128 x 8 x 3
    gemm_q3_kernel<<<gridq, 256>>>();
    dim3 gridcg(MROWS / BM, DDIM / BN);    // 128 x 8
    gemm_cg_kernel<<<gridcg, 256>>>();

    scan_kernel<<<(BATCH * DDIM) / 128, 128>>>(x, seqlen, bf, bc, bg, out);
}

// round 5
// speedup vs baseline: 1.6954x; 1.6954x over previous
#include <cstdint>
#include <cuda_runtime.h>
#include <cuda_bf16.h>
#include <mma.h>

using namespace nvcuda;

#define BATCH 32
#define TLEN  512
#define DDIM  1024
#define K2    2048             // doubled K for hi/lo interleaved copy-gate GEMM
#define MROWS (BATCH * TLEN)   // 16384

#define BM 128
#define BN 128
#define BK 32

// ---------------- scratch (__device__ globals; no allocation allowed) ----------------
__device__ __nv_bfloat16 g_aq [(size_t)MROWS * DDIM];   // quantized activations (ints, exact in bf16)
__device__ float         g_inv_s[MROWS];                // per-row 1/s
__device__ __nv_bfloat16 g_xhl[(size_t)MROWS * K2];     // interleaved hi/lo split of raw x
__device__ __nv_bfloat16 g_wf [(size_t)DDIM * DDIM];    // sign(W_f)
__device__ __nv_bfloat16 g_wc [(size_t)DDIM * DDIM];    // sign(W_c)
__device__ __nv_bfloat16 g_wgs[(size_t)DDIM * DDIM];    // sign(W_g)
__device__ __nv_bfloat16 g_wg2[(size_t)DDIM * K2];      // W_g rows duplicated along K (for hi/lo)
__device__ float g_F [(size_t)MROWS * DDIM];            // ACTIVATED gates (fp32)
__device__ float g_C [(size_t)MROWS * DDIM];
__device__ float g_G [(size_t)MROWS * DDIM];
__device__ float g_CG[(size_t)MROWS * DDIM];

// ---------------- MUFU-free sigmoid: FMA/ALU pipes only ----------------
// s = 1/(1 + 2^(-z*log2e)); 2^v via magic-round + deg-5 Taylor; rcp via bit-seed + 3 Newton.
__device__ __forceinline__ float fast_sigmoid(float z) {
    float v = -z * 1.4426950408889634f;
    v = fminf(fmaxf(v, -126.0f), 126.0f);
    float vr = v + 12582912.0f;                  // 1.5*2^23: round-to-nearest-int
    int   n  = __float_as_int(vr) - 0x4B400000;  // integer part
    float r  = v - (vr - 12582912.0f);           // remainder in [-0.5, 0.5]
    float p  = 1.33336e-3f;
    p = fmaf(p, r, 9.61813e-3f);
    p = fmaf(p, r, 5.55041e-2f);
    p = fmaf(p, r, 2.40226507e-1f);
    p = fmaf(p, r, 6.93147181e-1f);
    p = fmaf(p, r, 1.0f);
    float t = p * __int_as_float((n + 127) << 23);   // 2^v
    float w = 1.0f + t;
    float y = __int_as_float(0x7EF311C3 - __float_as_int(w));  // ~rcp seed
    y = y * (2.0f - w * y);
    y = y * (2.0f - w * y);
    y = y * (2.0f - w * y);
    return y;
}

__device__ __forceinline__ void cp_async16(void* smem, const void* gmem) {
    uint32_t s = (uint32_t)__cvta_generic_to_shared(smem);
    asm volatile("cp.async.cg.shared.global [%0], [%1], 16;\n" :: "r"(s), "l"(gmem));
}
__device__ __forceinline__ void cp_commit() { asm volatile("cp.async.commit_group;\n"); }
template <int N>
__device__ __forceinline__ void cp_wait() { asm volatile("cp.async.wait_group %0;\n" :: "n"(N)); }

// ---------------- weight conversion ----------------
__global__ void conv_w_kernel(const float* __restrict__ wf,
                              const float* __restrict__ wc,
                              const float* __restrict__ wg) {
    int i = blockIdx.x * 256 + threadIdx.x;
    if (i >= DDIM * DDIM) return;
    float a = wf[i], b = wc[i], c = wg[i];
    g_wf [i] = __float2bfloat16((a > 0.f) ? 1.f : ((a < 0.f) ? -1.f : 0.f));
    g_wc [i] = __float2bfloat16((b > 0.f) ? 1.f : ((b < 0.f) ? -1.f : 0.f));
    g_wgs[i] = __float2bfloat16((c > 0.f) ? 1.f : ((c < 0.f) ? -1.f : 0.f));
    __nv_bfloat16 cb = __float2bfloat16(c);   // ternary -> exact in bf16
    int n = i >> 10, j = i & 1023;
    size_t o2 = (size_t)n * K2 + 2 * j;
    g_wg2[o2] = cb; g_wg2[o2 + 1] = cb;
}

// ---------------- rmsnorm + act_quant + hi/lo split (one block per row) ----------------
__global__ __launch_bounds__(256) void prep_kernel(const float* __restrict__ x,
                                                   const float* __restrict__ scale) {
    __shared__ float red[256];
    int m = blockIdx.x;
    int t = threadIdx.x;
    const float4* xr = (const float4*)(x + (size_t)m * DDIM);
    float4 xv = xr[t];
    float4 sv = ((const float4*)scale)[t];

    float ss = xv.x * xv.x + xv.y * xv.y + xv.z * xv.z + xv.w * xv.w;
    red[t] = ss; __syncthreads();
    for (int s = 128; s > 0; s >>= 1) { if (t < s) red[t] += red[t + s]; __syncthreads(); }
    float rstd = rsqrtf(red[0] * (1.0f / DDIM) + 1e-5f);
    __syncthreads();

    float y0 = sv.x * xv.x * rstd, y1 = sv.y * xv.y * rstd;
    float y2 = sv.z * xv.z * rstd, y3 = sv.w * xv.w * rstd;
    float am = fmaxf(fmaxf(fabsf(y0), fabsf(y1)), fmaxf(fabsf(y2), fabsf(y3)));
    red[t] = am; __syncthreads();
    for (int s = 128; s > 0; s >>= 1) { if (t < s) red[t] = fmaxf(red[t], red[t + s]); __syncthreads(); }
    float amax = red[0];

    float s_q = fminf(fmaxf(127.0f / (amax + 1e-5f), 0.001f), 1000.0f);
    if (t == 0) g_inv_s[m] = 1.0f / s_q;

    float q0 = fminf(fmaxf(rintf(s_q * y0), -128.f), 127.f);
    float q1 = fminf(fmaxf(rintf(s_q * y1), -128.f), 127.f);
    float q2 = fminf(fmaxf(rintf(s_q * y2), -128.f), 127.f);
    float q3 = fminf(fmaxf(rintf(s_q * y3), -128.f), 127.f);

    union { __nv_bfloat16 h[4]; uint2 u; } pq;
    pq.h[0] = __float2bfloat16(q0); pq.h[1] = __float2bfloat16(q1);
    pq.h[2] = __float2bfloat16(q2); pq.h[3] = __float2bfloat16(q3);

    union { __nv_bfloat16 h[8]; uint4 u; } phl;
    float xa[4] = {xv.x, xv.y, xv.z, xv.w};
#pragma unroll
    for (int i = 0; i < 4; i++) {
        __nv_bfloat16 hi = __float2bfloat16(xa[i]);
        phl.h[2 * i]     = hi;
        phl.h[2 * i + 1] = __float2bfloat16(xa[i] - __bfloat162float(hi));
    }
    *(uint2*)&g_aq [(size_t)m * DDIM + t * 4]  = pq.u;
    *(uint4*)&g_xhl[(size_t)m * K2   + t * 8]  = phl.u;
}

// ---------------- 3 quantized GEMMs fused (blockIdx.z), 2-stage cp.async pipeline ------
// Epilogue: z = acc*inv_s + bias; MODE 0/2: sigmoid, MODE 1: silu. MUFU-free activation.
#define POOL_Q (2*BM*(BK+8)*2 + 2*BK*(BN+8)*2)   // 37888 bytes

__global__ __launch_bounds__(256) void gemm_q3_kernel(const float* __restrict__ bf_,
                                                      const float* __restrict__ bc_,
                                                      const float* __restrict__ bg_) {
    int mode = blockIdx.z;
    const __nv_bfloat16* __restrict__ W = (mode == 0) ? g_wf : (mode == 1) ? g_wc : g_wgs;
    float* __restrict__ out  = (mode == 0) ? g_F : (mode == 1) ? g_C : g_G;
    const float* __restrict__ bias = (mode == 0) ? bf_ : (mode == 1) ? bc_ : bg_;

    __shared__ __align__(16) char pool[POOL_Q];
    auto As = reinterpret_cast<__nv_bfloat16(*)[BM][BK + 8]>(pool);
    auto Bs = reinterpret_cast<__nv_bfloat16(*)[BK][BN + 8]>(pool + 2 * BM * (BK + 8) * 2);

    int tid = threadIdx.x;
    int warpId = tid >> 5;
    int lane = tid & 31;
    int wm = warpId & 3, wn = warpId >> 2;        // 4x2 warps, warp tile 32x64
    int bm = blockIdx.x * BM, bn = blockIdx.y * BN;

    wmma::fragment<wmma::accumulator, 16, 16, 16, float> acc[2][4];
#pragma unroll
    for (int i = 0; i < 2; i++)
#pragma unroll
        for (int j = 0; j < 4; j++) wmma::fill_fragment(acc[i][j], 0.0f);

    auto issue = [&](int k0, int buf) {
#pragma unroll
        for (int i = 0; i < 2; i++) {
            int ci = tid + i * 256;
            int r  = ci >> 2,  c8  = (ci & 3)  * 8;
            cp_async16(&As[buf][r][c8], &g_aq[(size_t)(bm + r) * DDIM + k0 + c8]);
            int rb = ci >> 4,  cb8 = (ci & 15) * 8;
            cp_async16(&Bs[buf][rb][cb8], &W[(size_t)(k0 + rb) * DDIM + bn + cb8]);
        }
    };

    issue(0, 0); cp_commit();
    const int NK = DDIM / BK;  // 32
    for (int kt = 0; kt < NK; ++kt) {
        if (kt + 1 < NK) { issue((kt + 1) * BK, (kt + 1) & 1); cp_commit(); cp_wait<1>(); }
        else             { cp_wait<0>(); }
        __syncthreads();
        int buf = kt & 1;
#pragma unroll
        for (int ks = 0; ks < BK; ks += 16) {
            wmma::fragment<wmma::matrix_a, 16, 16, 16, __nv_bfloat16, wmma::row_major> af[2];
            wmma::fragment<wmma::matrix_b, 16, 16, 16, __nv_bfloat16, wmma::row_major> bfr[4];
#pragma unroll
            for (int i = 0; i < 2; i++)
                wmma::load_matrix_sync(af[i], &As[buf][wm * 32 + i * 16][ks], BK + 8);
#pragma unroll
            for (int j = 0; j < 4; j++)
                wmma::load_matrix_sync(bfr[j], &Bs[buf][ks][wn * 64 + j * 16], BN + 8);
#pragma unroll
            for (int i = 0; i < 2; i++)
#pragma unroll
                for (int j = 0; j < 4; j++)
                    wmma::mma_sync(acc[i][j], af[i], bfr[j], acc[i][j]);
        }
        __syncthreads();
    }

    // epilogue: stage 16x16 fp32 tile in (reused) smem for row/col mapping
    float* sp = (float*)pool + warpId * 16 * 20;
#pragma unroll
    for (int i = 0; i < 2; i++)
#pragma unroll
        for (int j = 0; j < 4; j++) {
            wmma::store_matrix_sync(sp, acc[i][j], 20, wmma::mem_row_major);
            __syncwarp();
#pragma unroll
            for (int e = 0; e < 8; e++) {
                int idx = lane + e * 32;
                int r = idx >> 4, c = idx & 15;
                int gm = bm + wm * 32 + i * 16 + r;
                int gn = bn + wn * 64 + j * 16 + c;
                float z = sp[r * 20 + c] * g_inv_s[gm] + bias[gn];
                float s = fast_sigmoid(z);
                out[(size_t)gm * DDIM + gn] = (mode == 1) ? z * s : s;
            }
            __syncwarp();
        }
}

// ---------------- copy-gate GEMM: CG = sigmoid(x @ Wg^T), interleaved hi/lo (K=2048) ----
#define POOL_CG (2*BM*(BK+8)*2 + 2*BN*(BK+8)*2)   // 40960 bytes

__global__ __launch_bounds__(256) void gemm_cg_kernel() {
    __shared__ __align__(16) char pool[POOL_CG];
    auto As = reinterpret_cast<__nv_bfloat16(*)[BM][BK + 8]>(pool);
    auto Bs = reinterpret_cast<__nv_bfloat16(*)[BN][BK + 8]>(pool + 2 * BM * (BK + 8) * 2);

    int tid = threadIdx.x;
    int warpId = tid >> 5;
    int lane = tid & 31;
    int wm = warpId & 3, wn = warpId >> 2;
    int bm = blockIdx.x * BM, bn = blockIdx.y * BN;

    wmma::fragment<wmma::accumulator, 16, 16, 16, float> acc[2][4];
#pragma unroll
    for (int i = 0; i < 2; i++)
#pragma unroll
        for (int j = 0; j < 4; j++) wmma::fill_fragment(acc[i][j], 0.0f);

    auto issue = [&](int k0, int buf) {
#pragma unroll
        for (int i = 0; i < 2; i++) {
            int ci = tid + i * 256;
            int r = ci >> 2, c8 = (ci & 3) * 8;
            cp_async16(&As[buf][r][c8], &g_xhl[(size_t)(bm + r) * K2 + k0 + c8]);
            cp_async16(&Bs[buf][r][c8], &g_wg2[(size_t)(bn + r) * K2 + k0 + c8]);
        }
    };

    issue(0, 0); cp_commit();
    const int NK = K2 / BK;  // 64
    for (int kt = 0; kt < NK; ++kt) {
        if (kt + 1 < NK) { issue((kt + 1) * BK, (kt + 1) & 1); cp_commit(); cp_wait<1>(); }
        else             { cp_wait<0>(); }
        __syncthreads();
        int buf = kt & 1;
#pragma unroll
        for (int ks = 0; ks < BK; ks += 16) {
            wmma::fragment<wmma::matrix_a, 16, 16, 16, __nv_bfloat16, wmma::row_major> af[2];
            wmma::fragment<wmma::matrix_b, 16, 16, 16, __nv_bfloat16, wmma::col_major> bfr[4];
#pragma unroll
            for (int i = 0; i < 2; i++)
                wmma::load_matrix_sync(af[i], &As[buf][wm * 32 + i * 16][ks], BK + 8);
#pragma unroll
            for (int j = 0; j < 4; j++)
                wmma::load_matrix_sync(bfr[j], &Bs[buf][wn * 64 + j * 16][ks], BK + 8);
#pragma unroll
            for (int i = 0; i < 2; i++)
#pragma unroll
                for (int j = 0; j < 4; j++)
                    wmma::mma_sync(acc[i][j], af[i], bfr[j], acc[i][j]);
        }
        __syncthreads();
    }

    float* sp = (float*)pool + warpId * 16 * 20;
#pragma unroll
    for (int i = 0; i < 2; i++)
#pragma unroll
        for (int j = 0; j < 4; j++) {
            wmma::store_matrix_sync(sp, acc[i][j], 20, wmma::mem_row_major);
            __syncwarp();
#pragma unroll
            for (int e = 0; e < 8; e++) {
                int idx = lane + e * 32;
                int r = idx >> 4, c = idx & 15;
                int gm = bm + wm * 32 + i * 16 + r;
                int gn = bn + wn * 64 + j * 16 + c;
                g_CG[(size_t)gm * DDIM + gn] = fast_sigmoid(sp[r * 20 + c]);
            }
            __syncwarp();
        }
}

// ---------------- elementwise recurrence (pure FMA; gates pre-activated) ----------------
__global__ __launch_bounds__(128) void scan_kernel(const float* __restrict__ x,
                                                   const int* __restrict__ seqlen,
                                                   float* __restrict__ out) {
    int gid = blockIdx.x * blockDim.x + threadIdx.x;  // 0 .. 32767
    int b = gid >> 10;
    int d = gid & (DDIM - 1);
    int len = seqlen[b];
    size_t base = ((size_t)b * TLEN) * DDIM + d;
    float h = 0.0f;
#pragma unroll 8
    for (int t = 0; t < TLEN; t++) {
        size_t off = base + (size_t)t * DDIM;
        float f  = g_F[off];
        float c  = g_C[off];
        float g  = g_G[off];
        float cg = g_CG[off];
        float xv = x[off];
        float hn = f * h + (1.0f - f) * c;
        float o  = g * hn;
        h = cg * xv + (1.0f - cg) * hn;
        out[off] = (t < len) ? o : 0.0f;
    }
}

// ---------------- launcher ----------------
extern "C" void kernel_launch(void* const* d_in, const int* in_sizes, int n_in,
                              void* d_out, int out_size) {
    const float* x      = (const float*)d_in[0];
    const int*   seqlen = (const int*)  d_in[1];
    const float* scale  = (const float*)d_in[2];
    const float* Wf     = (const float*)d_in[3];
    const float* Wc     = (const float*)d_in[4];
    const float* Wg     = (const float*)d_in[5];
    const float* bf     = (const float*)d_in[6];
    const float* bc     = (const float*)d_in[7];
    const float* bg     = (const float*)d_in[8];
    float* out = (float*)d_out;

    conv_w_kernel<<<(DDIM * DDIM + 255) / 256, 256>>>(Wf, Wc, Wg);
    prep_kernel<<<MROWS, 256>>>(x, scale);

    dim3 gridq(MROWS / BM, DDIM / BN, 3);  // 128 x 8 x 3
    gemm_q3_kernel<<<gridq, 256>>>(bf, bc, bg);
    dim3 gridcg(MROWS / BM, DDIM / BN);    // 128 x 8
    gemm_cg_kernel<<<gridcg, 256>>>();

    scan_kernel<<<(BATCH * DDIM) / 128, 128>>>(x, seqlen, out);
}

// round 7
// speedup vs baseline: 1.8117x; 1.0686x over previous
#include <cstdint>
#include <cuda_runtime.h>
#include <cuda_bf16.h>
#include <cuda_fp16.h>
#include <mma.h>

using namespace nvcuda;

#define BATCH 32
#define TLEN  512
#define DDIM  1024
#define K2    2048             // doubled K for hi/lo interleaved copy-gate GEMM
#define MROWS (BATCH * TLEN)   // 16384

#define BM 128
#define BN 128
#define BKI 64                 // int8 GEMM k-tile
#define BK  32                 // bf16 (cg) k-tile

// ---------------- scratch (__device__ globals; no allocation allowed) ----------------
__device__ signed char   g_aq8[(size_t)MROWS * DDIM];   // quantized activations, int8 (exact)
__device__ float         g_inv_s[MROWS];                // per-row 1/s
__device__ __nv_bfloat16 g_xhl[(size_t)MROWS * K2];     // interleaved hi/lo split of raw x
__device__ signed char   g_w8f[(size_t)DDIM * DDIM];    // sign(W_f) int8, [k][n]
__device__ signed char   g_w8c[(size_t)DDIM * DDIM];    // sign(W_c)
__device__ signed char   g_w8g[(size_t)DDIM * DDIM];    // sign(W_g)
__device__ __nv_bfloat16 g_wg2[(size_t)DDIM * K2];      // W_g rows duplicated along K (hi/lo)
__device__ __half g_F [(size_t)MROWS * DDIM];           // ACTIVATED gates (fp16)
__device__ __half g_C [(size_t)MROWS * DDIM];
__device__ __half g_G [(size_t)MROWS * DDIM];
__device__ __half g_CG[(size_t)MROWS * DDIM];

// ---------------- MUFU-free sigmoid: FMA/ALU pipes only ----------------
__device__ __forceinline__ float fast_sigmoid(float z) {
    float v = -z * 1.4426950408889634f;
    v = fminf(fmaxf(v, -126.0f), 126.0f);
    float vr = v + 12582912.0f;                  // 1.5*2^23: round-to-nearest-int
    int   n  = __float_as_int(vr) - 0x4B400000;  // integer part
    float r  = v - (vr - 12582912.0f);           // remainder in [-0.5, 0.5]
    float p  = 1.33336e-3f;
    p = fmaf(p, r, 9.61813e-3f);
    p = fmaf(p, r, 5.55041e-2f);
    p = fmaf(p, r, 2.40226507e-1f);
    p = fmaf(p, r, 6.93147181e-1f);
    p = fmaf(p, r, 1.0f);
    float t = p * __int_as_float((n + 127) << 23);   // 2^v
    float w = 1.0f + t;
    float y = __int_as_float(0x7EF311C3 - __float_as_int(w));  // ~rcp seed
    y = y * (2.0f - w * y);
    y = y * (2.0f - w * y);
    y = y * (2.0f - w * y);
    return y;
}

__device__ __forceinline__ void cp_async16(void* smem, const void* gmem) {
    uint32_t s = (uint32_t)__cvta_generic_to_shared(smem);
    asm volatile("cp.async.cg.shared.global [%0], [%1], 16;\n" :: "r"(s), "l"(gmem));
}
__device__ __forceinline__ void cp_commit() { asm volatile("cp.async.commit_group;\n"); }
template <int N>
__device__ __forceinline__ void cp_wait() { asm volatile("cp.async.wait_group %0;\n" :: "n"(N)); }

// ---------------- weight conversion ----------------
__global__ void conv_w_kernel(const float* __restrict__ wf,
                              const float* __restrict__ wc,
                              const float* __restrict__ wg) {
    int i = blockIdx.x * 256 + threadIdx.x;
    if (i >= DDIM * DDIM) return;
    float a = wf[i], b = wc[i], c = wg[i];
    g_w8f[i] = (a > 0.f) ? 1 : ((a < 0.f) ? -1 : 0);
    g_w8c[i] = (b > 0.f) ? 1 : ((b < 0.f) ? -1 : 0);
    g_w8g[i] = (c > 0.f) ? 1 : ((c < 0.f) ? -1 : 0);
    __nv_bfloat16 cb = __float2bfloat16(c);   // ternary -> exact in bf16
    int n = i >> 10, j = i & 1023;
    size_t o2 = (size_t)n * K2 + 2 * j;
    g_wg2[o2] = cb; g_wg2[o2 + 1] = cb;
}

// ---------------- rmsnorm + act_quant + hi/lo split (one block per row) ----------------
__global__ __launch_bounds__(256) void prep_kernel(const float* __restrict__ x,
                                                   const float* __restrict__ scale) {
    __shared__ float red[256];
    int m = blockIdx.x;
    int t = threadIdx.x;
    const float4* xr = (const float4*)(x + (size_t)m * DDIM);
    float4 xv = xr[t];
    float4 sv = ((const float4*)scale)[t];

    float ss = xv.x * xv.x + xv.y * xv.y + xv.z * xv.z + xv.w * xv.w;
    red[t] = ss; __syncthreads();
    for (int s = 128; s > 0; s >>= 1) { if (t < s) red[t] += red[t + s]; __syncthreads(); }
    float rstd = rsqrtf(red[0] * (1.0f / DDIM) + 1e-5f);
    __syncthreads();

    float y0 = sv.x * xv.x * rstd, y1 = sv.y * xv.y * rstd;
    float y2 = sv.z * xv.z * rstd, y3 = sv.w * xv.w * rstd;
    float am = fmaxf(fmaxf(fabsf(y0), fabsf(y1)), fmaxf(fabsf(y2), fabsf(y3)));
    red[t] = am; __syncthreads();
    for (int s = 128; s > 0; s >>= 1) { if (t < s) red[t] = fmaxf(red[t], red[t + s]); __syncthreads(); }
    float amax = red[0];

    float s_q = fminf(fmaxf(127.0f / (amax + 1e-5f), 0.001f), 1000.0f);
    if (t == 0) g_inv_s[m] = 1.0f / s_q;

    float q0 = fminf(fmaxf(rintf(s_q * y0), -128.f), 127.f);
    float q1 = fminf(fmaxf(rintf(s_q * y1), -128.f), 127.f);
    float q2 = fminf(fmaxf(rintf(s_q * y2), -128.f), 127.f);
    float q3 = fminf(fmaxf(rintf(s_q * y3), -128.f), 127.f);

    union { signed char c[4]; uint32_t u; } pq;
    pq.c[0] = (signed char)q0; pq.c[1] = (signed char)q1;
    pq.c[2] = (signed char)q2; pq.c[3] = (signed char)q3;

    union { __nv_bfloat16 h[8]; uint4 u; } phl;
    float xa[4] = {xv.x, xv.y, xv.z, xv.w};
#pragma unroll
    for (int i = 0; i < 4; i++) {
        __nv_bfloat16 hi = __float2bfloat16(xa[i]);
        phl.h[2 * i]     = hi;
        phl.h[2 * i + 1] = __float2bfloat16(xa[i] - __bfloat162float(hi));
    }
    *(uint32_t*)&g_aq8[(size_t)m * DDIM + t * 4] = pq.u;
    *(uint4*)   &g_xhl[(size_t)m * K2   + t * 8] = phl.u;
}

// ---------------- 3 quantized GEMMs (int8 IMMA, exact), fused via blockIdx.z ----------
// 2-stage cp.async, BK=64. Epilogue: z = acc*inv_s + bias -> sigmoid/silu -> fp16.
#define AQ_STRIDE (BKI + 16)            // 80 int8 elems per row (16B-mult)
#define BQ_STRIDE (BN + 16)             // 144
#define POOL_Q (2*BM*AQ_STRIDE + 2*BKI*BQ_STRIDE)   // 20480 + 18432 = 38912 B

__global__ __launch_bounds__(256) void gemm_q3_kernel(const float* __restrict__ bf_,
                                                      const float* __restrict__ bc_,
                                                      const float* __restrict__ bg_) {
    int mode = blockIdx.z;
    const signed char* __restrict__ W = (mode == 0) ? g_w8f : (mode == 1) ? g_w8c : g_w8g;
    __half* __restrict__ out = (mode == 0) ? g_F : (mode == 1) ? g_C : g_G;
    const float* __restrict__ bias = (mode == 0) ? bf_ : (mode == 1) ? bc_ : bg_;

    __shared__ __align__(16) char pool[POOL_Q];
    auto As = reinterpret_cast<signed char(*)[BM][AQ_STRIDE]>(pool);
    auto Bs = reinterpret_cast<signed char(*)[BKI][BQ_STRIDE]>(pool + 2 * BM * AQ_STRIDE);

    int tid = threadIdx.x;
    int warpId = tid >> 5;
    int lane = tid & 31;
    int wm = warpId & 3, wn = warpId >> 2;        // 4x2 warps, warp tile 32x64
    int bm = blockIdx.x * BM, bn = blockIdx.y * BN;

    wmma::fragment<wmma::accumulator, 16, 16, 16, int> acc[2][4];
#pragma unroll
    for (int i = 0; i < 2; i++)
#pragma unroll
        for (int j = 0; j < 4; j++) wmma::fill_fragment(acc[i][j], 0);

    // per stage: A 128x64 int8 = 512 cp16, B 64x128 int8 = 512 cp16; 4 per thread
    auto issue = [&](int k0, int buf) {
#pragma unroll
        for (int i = 0; i < 2; i++) {
            int ci = tid + i * 256;                       // 0..511
            int r   = ci >> 2,  c16  = (ci & 3) * 16;     // A: 4 chunks/row
            cp_async16(&As[buf][r][c16], &g_aq8[(size_t)(bm + r) * DDIM + k0 + c16]);
            int rb  = ci >> 3,  cb16 = (ci & 7) * 16;     // B: 8 chunks/row
            cp_async16(&Bs[buf][rb][cb16], &W[(size_t)(k0 + rb) * DDIM + bn + cb16]);
        }
    };

    issue(0, 0); cp_commit();
    const int NK = DDIM / BKI;  // 16
    for (int kt = 0; kt < NK; ++kt) {
        if (kt + 1 < NK) { issue((kt + 1) * BKI, (kt + 1) & 1); cp_commit(); cp_wait<1>(); }
        else             { cp_wait<0>(); }
        __syncthreads();
        int buf = kt & 1;
#pragma unroll
        for (int ks = 0; ks < BKI; ks += 16) {
            wmma::fragment<wmma::matrix_a, 16, 16, 16, signed char, wmma::row_major> af[2];
            wmma::fragment<wmma::matrix_b, 16, 16, 16, signed char, wmma::row_major> bfr[4];
#pragma unroll
            for (int i = 0; i < 2; i++)
                wmma::load_matrix_sync(af[i], &As[buf][wm * 32 + i * 16][ks], AQ_STRIDE);
#pragma unroll
            for (int j = 0; j < 4; j++)
                wmma::load_matrix_sync(bfr[j], &Bs[buf][ks][wn * 64 + j * 16], BQ_STRIDE);
#pragma unroll
            for (int i = 0; i < 2; i++)
#pragma unroll
                for (int j = 0; j < 4; j++)
                    wmma::mma_sync(acc[i][j], af[i], bfr[j], acc[i][j]);
        }
        __syncthreads();
    }

    // epilogue: stage 16x16 int tile in (reused) smem
    int* sp = (int*)pool + warpId * 16 * 20;
#pragma unroll
    for (int i = 0; i < 2; i++)
#pragma unroll
        for (int j = 0; j < 4; j++) {
            wmma::store_matrix_sync(sp, acc[i][j], 20, wmma::mem_row_major);
            __syncwarp();
#pragma unroll
            for (int e = 0; e < 8; e++) {
                int idx = lane + e * 32;
                int r = idx >> 4, c = idx & 15;
                int gm = bm + wm * 32 + i * 16 + r;
                int gn = bn + wn * 64 + j * 16 + c;
                float z = (float)sp[r * 20 + c] * g_inv_s[gm] + bias[gn];
                float s = fast_sigmoid(z);
                out[(size_t)gm * DDIM + gn] = __float2half_rn((mode == 1) ? z * s : s);
            }
            __syncwarp();
        }
}

// ---------------- copy-gate GEMM: CG = sigmoid(x @ Wg^T), interleaved hi/lo (K=2048) ----
#define POOL_CG (2*BM*(BK+8)*2 + 2*BN*(BK+8)*2)   // 40960 bytes

__global__ __launch_bounds__(256) void gemm_cg_kernel() {
    __shared__ __align__(16) char pool[POOL_CG];
    auto As = reinterpret_cast<__nv_bfloat16(*)[BM][BK + 8]>(pool);
    auto Bs = reinterpret_cast<__nv_bfloat16(*)[BN][BK + 8]>(pool + 2 * BM * (BK + 8) * 2);

    int tid = threadIdx.x;
    int warpId = tid >> 5;
    int lane = tid & 31;
    int wm = warpId & 3, wn = warpId >> 2;
    int bm = blockIdx.x * BM, bn = blockIdx.y * BN;

    wmma::fragment<wmma::accumulator, 16, 16, 16, float> acc[2][4];
#pragma unroll
    for (int i = 0; i < 2; i++)
#pragma unroll
        for (int j = 0; j < 4; j++) wmma::fill_fragment(acc[i][j], 0.0f);

    auto issue = [&](int k0, int buf) {
#pragma unroll
        for (int i = 0; i < 2; i++) {
            int ci = tid + i * 256;
            int r = ci >> 2, c8 = (ci & 3) * 8;
            cp_async16(&As[buf][r][c8], &g_xhl[(size_t)(bm + r) * K2 + k0 + c8]);
            cp_async16(&Bs[buf][r][c8], &g_wg2[(size_t)(bn + r) * K2 + k0 + c8]);
        }
    };

    issue(0, 0); cp_commit();
    const int NK = K2 / BK;  // 64
    for (int kt = 0; kt < NK; ++kt) {
        if (kt + 1 < NK) { issue((kt + 1) * BK, (kt + 1) & 1); cp_commit(); cp_wait<1>(); }
        else             { cp_wait<0>(); }
        __syncthreads();
        int buf = kt & 1;
#pragma unroll
        for (int ks = 0; ks < BK; ks += 16) {
            wmma::fragment<wmma::matrix_a, 16, 16, 16, __nv_bfloat16, wmma::row_major> af[2];
            wmma::fragment<wmma::matrix_b, 16, 16, 16, __nv_bfloat16, wmma::col_major> bfr[4];
#pragma unroll
            for (int i = 0; i < 2; i++)
                wmma::load_matrix_sync(af[i], &As[buf][wm * 32 + i * 16][ks], BK + 8);
#pragma unroll
            for (int j = 0; j < 4; j++)
                wmma::load_matrix_sync(bfr[j], &Bs[buf][wn * 64 + j * 16][ks], BK + 8);
#pragma unroll
            for (int i = 0; i < 2; i++)
#pragma unroll
                for (int j = 0; j < 4; j++)
                    wmma::mma_sync(acc[i][j], af[i], bfr[j], acc[i][j]);
        }
        __syncthreads();
    }

    float* sp = (float*)pool + warpId * 16 * 20;
#pragma unroll
    for (int i = 0; i < 2; i++)
#pragma unroll
        for (int j = 0; j < 4; j++) {
            wmma::store_matrix_sync(sp, acc[i][j], 20, wmma::mem_row_major);
            __syncwarp();
#pragma unroll
            for (int e = 0; e < 8; e++) {
                int idx = lane + e * 32;
                int r = idx >> 4, c = idx & 15;
                int gm = bm + wm * 32 + i * 16 + r;
                int gn = bn + wn * 64 + j * 16 + c;
                g_CG[(size_t)gm * DDIM + gn] = __float2half_rn(fast_sigmoid(sp[r * 20 + c]));
            }
            __syncwarp();
        }
}

// ---------------- elementwise recurrence (pure FMA; gates pre-activated, fp16) ----------
__global__ __launch_bounds__(128) void scan_kernel(const float* __restrict__ x,
                                                   const int* __restrict__ seqlen,
                                                   float* __restrict__ out) {
    int gid = blockIdx.x * blockDim.x + threadIdx.x;  // 0 .. 32767
    int b = gid >> 10;
    int d = gid & (DDIM - 1);
    int len = seqlen[b];
    size_t base = ((size_t)b * TLEN) * DDIM + d;
    float h = 0.0f;
#pragma unroll 8
    for (int t = 0; t < TLEN; t++) {
        size_t off = base + (size_t)t * DDIM;
        float f  = __half2float(g_F[off]);
        float c  = __half2float(g_C[off]);
        float g  = __half2float(g_G[off]);
        float cg = __half2float(g_CG[off]);
        float xv = x[off];
        float hn = f * h + (1.0f - f) * c;
        float o  = g * hn;
        h = cg * xv + (1.0f - cg) * hn;
        out[off] = (t < len) ? o : 0.0f;
    }
}

// ---------------- launcher ----------------
extern "C" void kernel_launch(void* const* d_in, const int* in_sizes, int n_in,
                              void* d_out, int out_size) {
    const float* x      = (const float*)d_in[0];
    const int*   seqlen = (const int*)  d_in[1];
    const float* scale  = (const float*)d_in[2];
    const float* Wf     = (const float*)d_in[3];
    const float* Wc     = (const float*)d_in[4];
    const float* Wg     = (const float*)d_in[5];
    const float* bf     = (const float*)d_in[6];
    const float* bc     = (const float*)d_in[7];
    const float* bg     = (const float*)d_in[8];
    float* out = (float*)d_out;

    conv_w_kernel<<<(DDIM * DDIM + 255) / 256, 256>>>(Wf, Wc, Wg);
    prep_kernel<<<MROWS, 256>>>(x, scale);

    dim3 gridq(MROWS / BM, DDIM / BN, 3);  // 128 x 8 x 3
    gemm_q3_kernel<<<gridq, 256>>>(bf, bc, bg);
    dim3 gridcg(MROWS / BM, DDIM / BN);    // 128 x 8
    gemm_cg_kernel<<<gridcg, 256>>>();

    scan_kernel<<<(BATCH * DDIM) / 128, 128>>>(x, seqlen, out);
}